// round 1
// baseline (speedup 1.0000x reference)
#include <cuda_runtime.h>

// Problem constants
#define BB 16
#define SS 1024
#define HH 4096
#define OO 4096
#define NN 8
#define RR 64
#define MTOT (BB * SS)   // 16384 total rows; rows [n*2048, (n+1)*2048) belong to adapter n

typedef unsigned long long ull;

// 4 MB scratch for the intermediate T = (data*mask*scale) @ A^T   [MTOT, RR]
__device__ float g_t[(size_t)MTOT * RR];

// ---- packed f32x2 helpers (ptxas won't auto-fuse; PTX-only path) ----
__device__ __forceinline__ ull pack2(float lo, float hi) {
    ull r;
    asm("mov.b64 %0, {%1, %2};" : "=l"(r) : "f"(lo), "f"(hi));
    return r;
}
__device__ __forceinline__ void unpack2(ull v, float& lo, float& hi) {
    asm("mov.b64 {%0, %1}, %2;" : "=f"(lo), "=f"(hi) : "l"(v));
}
__device__ __forceinline__ ull fma2(ull a, ull b, ull c) {
    ull d;
    asm("fma.rn.f32x2 %0, %1, %2, %3;" : "=l"(d) : "l"(a), "l"(b), "l"(c));
    return d;
}

// ============================================================================
// Stage 1: T[m, r] = scaling[n] * sum_h data[m,h]*mask[m,h] * A[n,r,h]
// Tile: 32 rows x 64 cols (all of R), K chunks of 32. 512 blocks, 256 thr.
// Micro-tile per thread: 2 rows x 4 cols, accumulated as f32x2 pairs.
// ============================================================================
__global__ __launch_bounds__(256) void lora_stage1_kernel(
    const float* __restrict__ data,
    const float* __restrict__ mask,
    const float* __restrict__ lora_a,
    const float* __restrict__ scalings)
{
    __shared__ float Xs[32][36];  // [m][k], +4 pad (row stride 144B, 16B-aligned)
    __shared__ float As[32][68];  // [k][r], +4 pad (row stride 272B, 8B-aligned)

    const int t  = threadIdx.x;
    const int m0 = blockIdx.x * 32;
    const int n  = m0 >> 11;          // m0 / 2048 -> adapter id (32 | 2048, uniform per block)
    const float sc = scalings[n];

    const int tx = t & 15;            // col group: cols tx*4 .. tx*4+3
    const int ty = t >> 4;            // row group: rows ty*2, ty*2+1

    const int xrow = t >> 3;          // X-tile loader: row 0..31
    const int xkq  = t & 7;           // float4 index within 32-wide k chunk

    ull c00 = 0, c01 = 0, c10 = 0, c11 = 0;

    const float* a_base = lora_a + (size_t)n * RR * HH;

    for (int h0 = 0; h0 < HH; h0 += 32) {
        // ---- load X tile (fold in mask and scaling) : 1 float4 per thread ----
        {
            size_t gi = (size_t)(m0 + xrow) * HH + h0 + xkq * 4;
            float4 d4 = *(const float4*)(data + gi);
            float4 m4 = *(const float4*)(mask + gi);
            float4 x4 = make_float4(d4.x * m4.x * sc, d4.y * m4.y * sc,
                                    d4.z * m4.z * sc, d4.w * m4.w * sc);
            *(float4*)&Xs[xrow][xkq * 4] = x4;
        }
        // ---- load A tile transposed to [k][r] : 2 float4 per thread ----
        #pragma unroll
        for (int i = 0; i < 2; i++) {
            int idx = t + i * 256;            // 0..511 over (r, kq)
            int r   = idx >> 3;               // 0..63
            int kq  = idx & 7;                // 0..7
            float4 a4 = *(const float4*)(a_base + (size_t)r * HH + h0 + kq * 4);
            As[kq * 4 + 0][r] = a4.x;
            As[kq * 4 + 1][r] = a4.y;
            As[kq * 4 + 2][r] = a4.z;
            As[kq * 4 + 3][r] = a4.w;
        }
        __syncthreads();

        #pragma unroll
        for (int kk = 0; kk < 32; kk++) {
            float a0 = Xs[ty * 2 + 0][kk];
            float a1 = Xs[ty * 2 + 1][kk];
            ull A0 = pack2(a0, a0);
            ull A1 = pack2(a1, a1);
            ull b01 = *(const ull*)&As[kk][tx * 4];
            ull b23 = *(const ull*)&As[kk][tx * 4 + 2];
            c00 = fma2(A0, b01, c00);
            c01 = fma2(A0, b23, c01);
            c10 = fma2(A1, b01, c10);
            c11 = fma2(A1, b23, c11);
        }
        __syncthreads();
    }

    // ---- write T ----
    float x0, x1, x2, x3;
    unpack2(c00, x0, x1); unpack2(c01, x2, x3);
    *(float4*)(g_t + (size_t)(m0 + ty * 2 + 0) * RR + tx * 4) = make_float4(x0, x1, x2, x3);
    unpack2(c10, x0, x1); unpack2(c11, x2, x3);
    *(float4*)(g_t + (size_t)(m0 + ty * 2 + 1) * RR + tx * 4) = make_float4(x0, x1, x2, x3);
}

// ============================================================================
// Stage 2: out[m, o] = result[m, o] + sum_r T[m, r] * B[n, o, r]
// Tile: 64 rows x 64 cols, K = 64 fully resident. grid (64, 256), 256 thr.
// Micro-tile per thread: 4 rows x 4 cols.
// ============================================================================
__global__ __launch_bounds__(256) void lora_stage2_kernel(
    const float* __restrict__ result,
    const float* __restrict__ lora_b,
    float* __restrict__ out)
{
    __shared__ float Ts[64][68];  // [m][r], +4 pad
    __shared__ float Bs[64][68];  // [r][o], +4 pad

    const int t  = threadIdx.x;
    const int o0 = blockIdx.x * 64;
    const int m0 = blockIdx.y * 64;
    const int n  = m0 >> 11;
    const int tx = t & 15;
    const int ty = t >> 4;

    // ---- load T tile [64 x 64] : 4 float4 per thread ----
    #pragma unroll
    for (int i = 0; i < 4; i++) {
        int idx = t + i * 256;
        int row = idx >> 4;
        int kq  = idx & 15;
        float4 v = *(const float4*)(g_t + (size_t)(m0 + row) * RR + kq * 4);
        *(float4*)&Ts[row][kq * 4] = v;
    }
    // ---- load B tile transposed to [r][o] : 4 float4 per thread ----
    const float* b_base = lora_b + (size_t)n * OO * RR;
    #pragma unroll
    for (int i = 0; i < 4; i++) {
        int idx = t + i * 256;
        int o   = idx >> 4;
        int rq  = idx & 15;
        float4 v = *(const float4*)(b_base + (size_t)(o0 + o) * RR + rq * 4);
        Bs[rq * 4 + 0][o] = v.x;
        Bs[rq * 4 + 1][o] = v.y;
        Bs[rq * 4 + 2][o] = v.z;
        Bs[rq * 4 + 3][o] = v.w;
    }
    __syncthreads();

    ull c[4][2];
    #pragma unroll
    for (int i = 0; i < 4; i++) { c[i][0] = 0; c[i][1] = 0; }

    #pragma unroll 16
    for (int kk = 0; kk < 64; kk++) {
        ull b01 = *(const ull*)&Bs[kk][tx * 4];
        ull b23 = *(const ull*)&Bs[kk][tx * 4 + 2];
        #pragma unroll
        for (int i = 0; i < 4; i++) {
            float a = Ts[ty * 4 + i][kk];
            ull A = pack2(a, a);
            c[i][0] = fma2(A, b01, c[i][0]);
            c[i][1] = fma2(A, b23, c[i][1]);
        }
    }

    // ---- epilogue: add residual, write out ----
    #pragma unroll
    for (int i = 0; i < 4; i++) {
        size_t gi = (size_t)(m0 + ty * 4 + i) * OO + o0 + tx * 4;
        float4 r4 = *(const float4*)(result + gi);
        float x0, x1, x2, x3;
        unpack2(c[i][0], x0, x1);
        unpack2(c[i][1], x2, x3);
        *(float4*)(out + gi) = make_float4(r4.x + x0, r4.y + x1, r4.z + x2, r4.w + x3);
    }
}

extern "C" void kernel_launch(void* const* d_in, const int* in_sizes, int n_in,
                              void* d_out, int out_size) {
    const float* result   = (const float*)d_in[0];
    const float* data     = (const float*)d_in[1];
    const float* mask     = (const float*)d_in[2];
    const float* lora_a   = (const float*)d_in[3];
    const float* lora_b   = (const float*)d_in[4];
    const float* scalings = (const float*)d_in[5];
    float* out = (float*)d_out;

    lora_stage1_kernel<<<MTOT / 32, 256>>>(data, mask, lora_a, scalings);

    dim3 g2(OO / 64, MTOT / 64);
    lora_stage2_kernel<<<g2, 256>>>(result, lora_b, out);
}

// round 2
// speedup vs baseline: 1.2594x; 1.2594x over previous
#include <cuda_runtime.h>

#define HH 4096
#define OO 4096
#define RR 64
#define MTOT 16384   // B*S; rows [n*2048,(n+1)*2048) -> adapter n

typedef unsigned long long ull;

// 4 MB scratch for T = (data*mask*scale) @ A^T   [MTOT, RR]
__device__ float g_t[(size_t)MTOT * RR];

// ---- packed f32x2 helpers ----
__device__ __forceinline__ ull pack2(float lo, float hi) {
    ull r;
    asm("mov.b64 %0, {%1, %2};" : "=l"(r) : "f"(lo), "f"(hi));
    return r;
}
__device__ __forceinline__ void unpack2(ull v, float& lo, float& hi) {
    asm("mov.b64 {%0, %1}, %2;" : "=f"(lo), "=f"(hi) : "l"(v));
}
__device__ __forceinline__ ull fma2(ull a, ull b, ull c) {
    ull d;
    asm("fma.rn.f32x2 %0, %1, %2, %3;" : "=l"(d) : "l"(a), "l"(b), "l"(c));
    return d;
}

// ============================================================================
// Stage 1: T[m,r] = sc[n] * sum_h (data*mask)[m,h] * A[n,r,h]
// Block tile 64(M) x 64(R), K-chunks of 32, 256 threads, 4x4 micro-tile.
// X stored duplicated (Xs[k][2m] = Xs[k][2m+1]) so LDS.64 gives (a,a) pairs.
// Register prefetch of next chunk overlaps LDG with compute.
// ============================================================================
__global__ __launch_bounds__(256) void lora_s1(
    const float* __restrict__ data,
    const float* __restrict__ mask,
    const float* __restrict__ lora_a,
    const float* __restrict__ scalings)
{
    __shared__ float Xs[32][130];  // [k][2m dup], pitch 130 (8B-aligned pairs)
    __shared__ float As[32][68];   // [k][r], pitch 68 (16B-aligned float4)

    const int t  = threadIdx.x;
    const int m0 = blockIdx.x * 64;
    const int n  = m0 >> 11;
    const float sc = scalings[n];

    const int tx = t & 15;         // col group: r = tx*4 .. tx*4+3
    const int ty = t >> 4;         // row group: m = ty*4 .. ty*4+3

    const int lm  = t >> 3;        // loader row 0..31 (slot1 adds +32)
    const int lkq = t & 7;         // loader float4 k-index 0..7

    const float* a_base = lora_a + (size_t)n * RR * HH;

    ull acc[4][2];
    #pragma unroll
    for (int i = 0; i < 4; i++) { acc[i][0] = 0; acc[i][1] = 0; }

    float4 d0, d1, q0, q1, a0, a1;

    // prefetch chunk 0
    {
        size_t gx0 = (size_t)(m0 + lm) * HH + lkq * 4;
        size_t gx1 = (size_t)(m0 + lm + 32) * HH + lkq * 4;
        d0 = __ldcs((const float4*)(data + gx0));
        q0 = __ldcs((const float4*)(mask + gx0));
        d1 = __ldcs((const float4*)(data + gx1));
        q1 = __ldcs((const float4*)(mask + gx1));
        a0 = *(const float4*)(a_base + (size_t)lm * HH + lkq * 4);
        a1 = *(const float4*)(a_base + (size_t)(lm + 32) * HH + lkq * 4);
    }

    for (int ch = 0; ch < 128; ch++) {
        __syncthreads();   // previous compute done reading smem

        // ---- store prefetched chunk to smem ----
        {
            const int kb = lkq * 4;
            float4 x;
            x.x = d0.x * q0.x * sc; x.y = d0.y * q0.y * sc;
            x.z = d0.z * q0.z * sc; x.w = d0.w * q0.w * sc;
            Xs[kb + 0][2*lm] = x.x; Xs[kb + 0][2*lm + 1] = x.x;
            Xs[kb + 1][2*lm] = x.y; Xs[kb + 1][2*lm + 1] = x.y;
            Xs[kb + 2][2*lm] = x.z; Xs[kb + 2][2*lm + 1] = x.z;
            Xs[kb + 3][2*lm] = x.w; Xs[kb + 3][2*lm + 1] = x.w;
            x.x = d1.x * q1.x * sc; x.y = d1.y * q1.y * sc;
            x.z = d1.z * q1.z * sc; x.w = d1.w * q1.w * sc;
            const int m2 = 2 * (lm + 32);
            Xs[kb + 0][m2] = x.x; Xs[kb + 0][m2 + 1] = x.x;
            Xs[kb + 1][m2] = x.y; Xs[kb + 1][m2 + 1] = x.y;
            Xs[kb + 2][m2] = x.z; Xs[kb + 2][m2 + 1] = x.z;
            Xs[kb + 3][m2] = x.w; Xs[kb + 3][m2 + 1] = x.w;
            As[kb + 0][lm] = a0.x; As[kb + 1][lm] = a0.y;
            As[kb + 2][lm] = a0.z; As[kb + 3][lm] = a0.w;
            As[kb + 0][lm + 32] = a1.x; As[kb + 1][lm + 32] = a1.y;
            As[kb + 2][lm + 32] = a1.z; As[kb + 3][lm + 32] = a1.w;
        }
        __syncthreads();

        // ---- prefetch next chunk (LDGs overlap with compute below) ----
        if (ch + 1 < 128) {
            const int h0 = (ch + 1) * 32;
            size_t gx0 = (size_t)(m0 + lm) * HH + h0 + lkq * 4;
            size_t gx1 = (size_t)(m0 + lm + 32) * HH + h0 + lkq * 4;
            d0 = __ldcs((const float4*)(data + gx0));
            q0 = __ldcs((const float4*)(mask + gx0));
            d1 = __ldcs((const float4*)(data + gx1));
            q1 = __ldcs((const float4*)(mask + gx1));
            a0 = *(const float4*)(a_base + (size_t)lm * HH + h0 + lkq * 4);
            a1 = *(const float4*)(a_base + (size_t)(lm + 32) * HH + h0 + lkq * 4);
        }

        // ---- compute 32 k-steps ----
        #pragma unroll 8
        for (int kk = 0; kk < 32; kk++) {
            ulonglong2 b = *(const ulonglong2*)&As[kk][tx * 4];
            #pragma unroll
            for (int i = 0; i < 4; i++) {
                ull ap = *(const ull*)&Xs[kk][2 * (ty * 4 + i)];
                acc[i][0] = fma2(ap, b.x, acc[i][0]);
                acc[i][1] = fma2(ap, b.y, acc[i][1]);
            }
        }
    }

    // ---- write T ----
    #pragma unroll
    for (int i = 0; i < 4; i++) {
        float x0, x1, x2, x3;
        unpack2(acc[i][0], x0, x1);
        unpack2(acc[i][1], x2, x3);
        *(float4*)(g_t + (size_t)(m0 + ty * 4 + i) * RR + tx * 4) =
            make_float4(x0, x1, x2, x3);
    }
}

// ============================================================================
// Stage 2: out[m,o] = result[m,o] + sum_r T[m,r] * B[n,o,r]
// Block tile 128(M) x 128(O), K=64 fully smem-resident, 256 threads,
// 8x8 micro-tile (rows ty*8.., cols {tx*4..+3} and {64+tx*4..+3}).
// 64 KB dynamic smem.
// ============================================================================
__global__ __launch_bounds__(256, 2) void lora_s2(
    const float* __restrict__ result,
    const float* __restrict__ lora_b,
    float* __restrict__ out)
{
    extern __shared__ float sm[];
    float* Ts = sm;               // [64][128]  (k-major)
    float* Bs = sm + 64 * 128;    // [64][128]  (k-major)

    const int t  = threadIdx.x;
    const int o0 = blockIdx.x * 128;
    const int m0 = blockIdx.y * 128;
    const int n  = m0 >> 11;
    const int tx = t & 15;
    const int ty = t >> 4;

    // ---- load T tile [128m x 64k] -> Ts[k][m] (conflict-free STS) ----
    #pragma unroll
    for (int i = 0; i < 8; i++) {
        int idx = t + i * 256;
        int m   = idx & 127;
        int kq  = idx >> 7;        // 0..15
        float4 v = *(const float4*)(g_t + (size_t)(m0 + m) * RR + kq * 4);
        Ts[(kq * 4 + 0) * 128 + m] = v.x;
        Ts[(kq * 4 + 1) * 128 + m] = v.y;
        Ts[(kq * 4 + 2) * 128 + m] = v.z;
        Ts[(kq * 4 + 3) * 128 + m] = v.w;
    }
    // ---- load B tile [128o x 64r] -> Bs[r][o] ----
    const float* b_base = lora_b + (size_t)n * OO * RR;
    #pragma unroll
    for (int i = 0; i < 8; i++) {
        int idx = t + i * 256;
        int o   = idx & 127;
        int rq  = idx >> 7;
        float4 v = *(const float4*)(b_base + (size_t)(o0 + o) * RR + rq * 4);
        Bs[(rq * 4 + 0) * 128 + o] = v.x;
        Bs[(rq * 4 + 1) * 128 + o] = v.y;
        Bs[(rq * 4 + 2) * 128 + o] = v.z;
        Bs[(rq * 4 + 3) * 128 + o] = v.w;
    }
    __syncthreads();

    ull c[8][4];
    #pragma unroll
    for (int i = 0; i < 8; i++)
        #pragma unroll
        for (int j = 0; j < 4; j++) c[i][j] = 0;

    #pragma unroll 4
    for (int kk = 0; kk < 64; kk++) {
        float4 av0 = *(const float4*)&Ts[kk * 128 + ty * 8];
        float4 av1 = *(const float4*)&Ts[kk * 128 + ty * 8 + 4];
        ulonglong2 bA = *(const ulonglong2*)&Bs[kk * 128 + tx * 4];
        ulonglong2 bB = *(const ulonglong2*)&Bs[kk * 128 + 64 + tx * 4];
        float av[8] = {av0.x, av0.y, av0.z, av0.w, av1.x, av1.y, av1.z, av1.w};
        #pragma unroll
        for (int i = 0; i < 8; i++) {
            ull ap = pack2(av[i], av[i]);
            c[i][0] = fma2(ap, bA.x, c[i][0]);
            c[i][1] = fma2(ap, bA.y, c[i][1]);
            c[i][2] = fma2(ap, bB.x, c[i][2]);
            c[i][3] = fma2(ap, bB.y, c[i][3]);
        }
    }

    // ---- epilogue: add residual, write ----
    #pragma unroll
    for (int i = 0; i < 8; i++) {
        size_t row = (size_t)(m0 + ty * 8 + i);
        size_t g0 = row * OO + o0 + tx * 4;
        float4 r0 = __ldcs((const float4*)(result + g0));
        float4 r1 = __ldcs((const float4*)(result + g0 + 64));
        float x0, x1, x2, x3;
        unpack2(c[i][0], x0, x1); unpack2(c[i][1], x2, x3);
        __stcs((float4*)(out + g0),
               make_float4(r0.x + x0, r0.y + x1, r0.z + x2, r0.w + x3));
        unpack2(c[i][2], x0, x1); unpack2(c[i][3], x2, x3);
        __stcs((float4*)(out + g0 + 64),
               make_float4(r1.x + x0, r1.y + x1, r1.z + x2, r1.w + x3));
    }
}

extern "C" void kernel_launch(void* const* d_in, const int* in_sizes, int n_in,
                              void* d_out, int out_size) {
    const float* result   = (const float*)d_in[0];
    const float* data     = (const float*)d_in[1];
    const float* mask     = (const float*)d_in[2];
    const float* lora_a   = (const float*)d_in[3];
    const float* lora_b   = (const float*)d_in[4];
    const float* scalings = (const float*)d_in[5];
    float* out = (float*)d_out;

    lora_s1<<<MTOT / 64, 256>>>(data, mask, lora_a, scalings);

    const int smem2 = 2 * 64 * 128 * sizeof(float);  // 64 KB
    cudaFuncSetAttribute(lora_s2, cudaFuncAttributeMaxDynamicSharedMemorySize, smem2);
    dim3 g2(OO / 128, MTOT / 128);
    lora_s2<<<g2, 256, smem2>>>(result, lora_b, out);
}

// round 4
// speedup vs baseline: 1.9496x; 1.5480x over previous
#include <cuda_runtime.h>
#include <cuda_fp16.h>
#include <cstdint>

#define HHC 4096
#define OOC 4096
#define RRC 64

// smem pitches (in halves)
#define XP 40   // X tile rows [128][32] -> pad 40
#define AP 40   // A tiles [64][32] -> pad 40
#define TP 72   // T [128][64] -> pad 72
#define BP 72   // B tiles [64][64] -> pad 72

// smem byte map:
//   P region (40960 B): phase1 buf b @ b*20480: X (10240) | Ah (5120) | Al (5120)
//                       phase2 buf b @ b*18432: Bh (9216) | Bl (9216)
//   T region @ 40960: [128][72] halves = 18432 B
#define SMEM_TOTAL (40960 + 18432)

__device__ __forceinline__ void hmma16816(float* c,
                                          uint32_t a0, uint32_t a1, uint32_t a2, uint32_t a3,
                                          uint32_t b0, uint32_t b1) {
    asm volatile(
        "mma.sync.aligned.m16n8k16.row.col.f32.f16.f16.f32 "
        "{%0,%1,%2,%3}, {%4,%5,%6,%7}, {%8,%9}, {%0,%1,%2,%3};"
        : "+f"(c[0]), "+f"(c[1]), "+f"(c[2]), "+f"(c[3])
        : "r"(a0), "r"(a1), "r"(a2), "r"(a3), "r"(b0), "r"(b1));
}

__device__ __forceinline__ uint32_t h2u(__half2 h) {
    return *reinterpret_cast<uint32_t*>(&h);
}

__global__ __launch_bounds__(256) void lora_fused(
    const float* __restrict__ result,
    const float* __restrict__ data,
    const float* __restrict__ mask,
    const float* __restrict__ lora_a,
    const float* __restrict__ lora_b,
    const float* __restrict__ scalings,
    float* __restrict__ out)
{
    extern __shared__ char smem[];
    __half* smh = reinterpret_cast<__half*>(smem);

    const int t    = threadIdx.x;
    const int w    = t >> 5;
    const int lane = t & 31;
    const int g    = lane >> 2;   // fragment row group 0..7
    const int t4   = lane & 3;    // fragment k/col group 0..3

    const int m0 = blockIdx.x * 128;
    const int n  = blockIdx.x >> 4;       // adapter id (16 CTAs per adapter)
    const float sc = __ldg(scalings + n);

    const int row0 = w * 16 + g;          // this thread's first m-row (CTA-local)

    // ======================== PHASE 1 ========================
    // T[128,64] = (data*mask*sc)[128,4096] @ A^T, K-chunks of 32.
    float accT[8][4];
    #pragma unroll
    for (int j = 0; j < 8; j++)
        #pragma unroll
        for (int k = 0; k < 4; k++) accT[j][k] = 0.f;

    const float* dbase = data + (size_t)m0 * HHC;
    const float* mbase = mask + (size_t)m0 * HHC;
    const float* abase = lora_a + (size_t)n * RRC * HHC;

    float4 dreg[4], mreg[4], areg[2];

    // prefetch chunk 0
    #pragma unroll
    for (int i = 0; i < 4; i++) {
        int idx = t + i * 256, row = idx >> 3, q = idx & 7;
        dreg[i] = __ldcs((const float4*)(dbase + (size_t)row * HHC + q * 4));
        mreg[i] = __ldcs((const float4*)(mbase + (size_t)row * HHC + q * 4));
    }
    #pragma unroll
    for (int i = 0; i < 2; i++) {
        int idx = t + i * 256, row = idx >> 3, q = idx & 7;
        areg[i] = *(const float4*)(abase + (size_t)row * HHC + q * 4);
    }

    for (int ch = 0; ch < 128; ch++) {
        const int b = ch & 1;
        __half* Xs = smh + b * 10240;          // halves
        __half* Ah = smh + b * 10240 + 5120;
        __half* Al = smh + b * 10240 + 7680;

        // ---- STS X (fold mask & scaling, cvt fp16) ----
        #pragma unroll
        for (int i = 0; i < 4; i++) {
            int idx = t + i * 256, row = idx >> 3, q = idx & 7;
            float4 d4 = dreg[i], m4 = mreg[i];
            __half2 h0 = __floats2half2_rn(d4.x * m4.x * sc, d4.y * m4.y * sc);
            __half2 h1 = __floats2half2_rn(d4.z * m4.z * sc, d4.w * m4.w * sc);
            *(uint2*)(Xs + row * XP + q * 4) = make_uint2(h2u(h0), h2u(h1));
        }
        // ---- STS A hi/lo ----
        #pragma unroll
        for (int i = 0; i < 2; i++) {
            int idx = t + i * 256, row = idx >> 3, q = idx & 7;
            float4 a4 = areg[i];
            __half2 h0 = __floats2half2_rn(a4.x, a4.y);
            __half2 h1 = __floats2half2_rn(a4.z, a4.w);
            float2 f0 = __half22float2(h0), f1 = __half22float2(h1);
            __half2 l0 = __floats2half2_rn(a4.x - f0.x, a4.y - f0.y);
            __half2 l1 = __floats2half2_rn(a4.z - f1.x, a4.w - f1.y);
            *(uint2*)(Ah + row * AP + q * 4) = make_uint2(h2u(h0), h2u(h1));
            *(uint2*)(Al + row * AP + q * 4) = make_uint2(h2u(l0), h2u(l1));
        }
        __syncthreads();

        // ---- prefetch next chunk ----
        if (ch + 1 < 128) {
            const int ho = (ch + 1) * 32;
            #pragma unroll
            for (int i = 0; i < 4; i++) {
                int idx = t + i * 256, row = idx >> 3, q = idx & 7;
                dreg[i] = __ldcs((const float4*)(dbase + (size_t)row * HHC + ho + q * 4));
                mreg[i] = __ldcs((const float4*)(mbase + (size_t)row * HHC + ho + q * 4));
            }
            #pragma unroll
            for (int i = 0; i < 2; i++) {
                int idx = t + i * 256, row = idx >> 3, q = idx & 7;
                areg[i] = *(const float4*)(abase + (size_t)row * HHC + ho + q * 4);
            }
        }

        // ---- MMA: 2 k16 steps ----
        #pragma unroll
        for (int s = 0; s < 2; s++) {
            const int kb = s * 16 + t4 * 2;
            uint32_t a0 = *(const uint32_t*)(Xs + row0 * XP + kb);
            uint32_t a1 = *(const uint32_t*)(Xs + (row0 + 8) * XP + kb);
            uint32_t a2 = *(const uint32_t*)(Xs + row0 * XP + kb + 8);
            uint32_t a3 = *(const uint32_t*)(Xs + (row0 + 8) * XP + kb + 8);
            #pragma unroll
            for (int j = 0; j < 8; j++) {
                const int nr = j * 8 + g;
                uint32_t bh0 = *(const uint32_t*)(Ah + nr * AP + kb);
                uint32_t bh1 = *(const uint32_t*)(Ah + nr * AP + kb + 8);
                hmma16816(accT[j], a0, a1, a2, a3, bh0, bh1);
                uint32_t bl0 = *(const uint32_t*)(Al + nr * AP + kb);
                uint32_t bl1 = *(const uint32_t*)(Al + nr * AP + kb + 8);
                hmma16816(accT[j], a0, a1, a2, a3, bl0, bl1);
            }
        }
    }

    // ---- quantize T into smem ----
    __half* Ts = smh + 20480;   // byte offset 40960
    #pragma unroll
    for (int j = 0; j < 8; j++) {
        __half2 h0 = __floats2half2_rn(accT[j][0], accT[j][1]);
        __half2 h1 = __floats2half2_rn(accT[j][2], accT[j][3]);
        *(uint32_t*)(Ts + row0 * TP + j * 8 + t4 * 2)       = h2u(h0);
        *(uint32_t*)(Ts + (row0 + 8) * TP + j * 8 + t4 * 2) = h2u(h1);
    }

    // ======================== PHASE 2 ========================
    // out[128, 4096] = result + T @ B^T, o-chunks of 64.
    const float* bbase = lora_b + (size_t)n * OOC * RRC;
    float4 breg[4];
    #pragma unroll
    for (int i = 0; i < 4; i++) {
        int idx = t + i * 256, row = idx >> 4, q = idx & 15;
        breg[i] = *(const float4*)(bbase + (size_t)row * RRC + q * 4);
    }
    __syncthreads();   // T visible; phase1 smem reads complete before B STS

    for (int oc = 0; oc < 64; oc++) {
        const int b = oc & 1;
        __half* Bh = smh + b * 9216;          // halves (byte b*18432)
        __half* Bl = smh + b * 9216 + 4608;
        const int o0 = oc * 64;

        // ---- STS B hi/lo ----
        #pragma unroll
        for (int i = 0; i < 4; i++) {
            int idx = t + i * 256, row = idx >> 4, q = idx & 15;
            float4 a4 = breg[i];
            __half2 h0 = __floats2half2_rn(a4.x, a4.y);
            __half2 h1 = __floats2half2_rn(a4.z, a4.w);
            float2 f0 = __half22float2(h0), f1 = __half22float2(h1);
            __half2 l0 = __floats2half2_rn(a4.x - f0.x, a4.y - f0.y);
            __half2 l1 = __floats2half2_rn(a4.z - f1.x, a4.w - f1.y);
            *(uint2*)(Bh + row * BP + q * 4) = make_uint2(h2u(h0), h2u(h1));
            *(uint2*)(Bl + row * BP + q * 4) = make_uint2(h2u(l0), h2u(l1));
        }
        __syncthreads();

        // ---- prefetch next B chunk ----
        if (oc + 1 < 64) {
            const int on = (oc + 1) * 64;
            #pragma unroll
            for (int i = 0; i < 4; i++) {
                int idx = t + i * 256, row = idx >> 4, q = idx & 15;
                breg[i] = *(const float4*)(bbase + (size_t)(on + row) * RRC + q * 4);
            }
        }

        // ---- MMA: K = 64 = 4 k16 steps ----
        float acc[8][4];
        #pragma unroll
        for (int j = 0; j < 8; j++)
            #pragma unroll
            for (int k = 0; k < 4; k++) acc[j][k] = 0.f;

        #pragma unroll
        for (int s = 0; s < 4; s++) {
            const int kb = s * 16 + t4 * 2;
            uint32_t a0 = *(const uint32_t*)(Ts + row0 * TP + kb);
            uint32_t a1 = *(const uint32_t*)(Ts + (row0 + 8) * TP + kb);
            uint32_t a2 = *(const uint32_t*)(Ts + row0 * TP + kb + 8);
            uint32_t a3 = *(const uint32_t*)(Ts + (row0 + 8) * TP + kb + 8);
            #pragma unroll
            for (int j = 0; j < 8; j++) {
                const int nr = j * 8 + g;
                uint32_t bh0 = *(const uint32_t*)(Bh + nr * BP + kb);
                uint32_t bh1 = *(const uint32_t*)(Bh + nr * BP + kb + 8);
                hmma16816(acc[j], a0, a1, a2, a3, bh0, bh1);
                uint32_t bl0 = *(const uint32_t*)(Bl + nr * BP + kb);
                uint32_t bl1 = *(const uint32_t*)(Bl + nr * BP + kb + 8);
                hmma16816(acc[j], a0, a1, a2, a3, bl0, bl1);
            }
        }

        // ---- epilogue: residual add + store ----
        #pragma unroll
        for (int j = 0; j < 8; j++) {
            const int ocol = o0 + j * 8 + t4 * 2;
            size_t gi0 = (size_t)(m0 + row0) * OOC + ocol;
            size_t gi1 = (size_t)(m0 + row0 + 8) * OOC + ocol;
            float2 r0 = __ldcs((const float2*)(result + gi0));
            float2 r1 = __ldcs((const float2*)(result + gi1));
            __stcs((float2*)(out + gi0), make_float2(r0.x + acc[j][0], r0.y + acc[j][1]));
            __stcs((float2*)(out + gi1), make_float2(r1.x + acc[j][2], r1.y + acc[j][3]));
        }
    }
}

extern "C" void kernel_launch(void* const* d_in, const int* in_sizes, int n_in,
                              void* d_out, int out_size) {
    const float* result   = (const float*)d_in[0];
    const float* data     = (const float*)d_in[1];
    const float* mask     = (const float*)d_in[2];
    const float* lora_a   = (const float*)d_in[3];
    const float* lora_b   = (const float*)d_in[4];
    const float* scalings = (const float*)d_in[5];
    float* out = (float*)d_out;

    cudaFuncSetAttribute(lora_fused, cudaFuncAttributeMaxDynamicSharedMemorySize, SMEM_TOTAL);
    lora_fused<<<128, 256, SMEM_TOTAL>>>(result, data, mask, lora_a, lora_b, scalings, out);
}

// round 5
// speedup vs baseline: 2.3947x; 1.2283x over previous
#include <cuda_runtime.h>
#include <cuda_fp16.h>
#include <cstdint>

#define HHC 4096
#define OOC 4096
#define RRC 64

// smem pitches (in halves)
#define XP 40   // X tile [64][32] -> pitch 40
#define AP 40   // A tiles [64][32] -> pitch 40
#define TP 72   // T [64][64] -> pitch 72
#define BP 72   // B tiles [64][64] -> pitch 72

// smem layout (halves):
//   phase1 buf b @ b*7680 : X(2560) | Ah(2560) | Al(2560)      (2 bufs: 15360 h)
//   phase2 buf b @ b*9216 : Bh(4608) | Bl(4608)                (2 bufs: 18432 h, overlaps phase1)
//   Ts @ 18432 : 64*72 = 4608 h
// total halves = 23040 -> 46080 bytes
#define SMEM_TOTAL 46080

__device__ __forceinline__ void hmma16816(float* c,
                                          uint32_t a0, uint32_t a1, uint32_t a2, uint32_t a3,
                                          uint32_t b0, uint32_t b1) {
    asm volatile(
        "mma.sync.aligned.m16n8k16.row.col.f32.f16.f16.f32 "
        "{%0,%1,%2,%3}, {%4,%5,%6,%7}, {%8,%9}, {%0,%1,%2,%3};"
        : "+f"(c[0]), "+f"(c[1]), "+f"(c[2]), "+f"(c[3])
        : "r"(a0), "r"(a1), "r"(a2), "r"(a3), "r"(b0), "r"(b1));
}

__device__ __forceinline__ uint32_t h2u(__half2 h) {
    return *reinterpret_cast<uint32_t*>(&h);
}

__global__ __launch_bounds__(256, 2) void lora_fused(
    const float* __restrict__ result,
    const float* __restrict__ data,
    const float* __restrict__ mask,
    const float* __restrict__ lora_a,
    const float* __restrict__ lora_b,
    const float* __restrict__ scalings,
    float* __restrict__ out)
{
    extern __shared__ char smem[];
    __half* smh = reinterpret_cast<__half*>(smem);

    const int t    = threadIdx.x;
    const int w    = t >> 5;
    const int lane = t & 31;
    const int g    = lane >> 2;   // fragment row 0..7
    const int t4   = lane & 3;    // fragment k/col quad 0..3

    const int wm = w & 3;         // M slab (16 rows)
    const int wn = w >> 2;        // N half (32 cols)

    const int m0 = blockIdx.x * 64;
    const int n  = blockIdx.x >> 5;        // 32 CTAs per adapter
    const float sc = __ldg(scalings + n);

    const int row0 = wm * 16 + g;          // CTA-local m-row

    // ======================== PHASE 1 ========================
    // T[64,64] = (data*mask*sc)[64,4096] @ A^T, K-chunks of 32.
    float accT[4][4];
    #pragma unroll
    for (int j = 0; j < 4; j++)
        #pragma unroll
        for (int k = 0; k < 4; k++) accT[j][k] = 0.f;

    const float* dbase = data + (size_t)m0 * HHC;
    const float* mbase = mask + (size_t)m0 * HHC;
    const float* abase = lora_a + (size_t)n * RRC * HHC;

    float4 dreg[2], mreg[2], areg[2];

    #pragma unroll
    for (int i = 0; i < 2; i++) {
        int idx = t + i * 256, row = idx >> 3, q = idx & 7;
        dreg[i] = __ldcs((const float4*)(dbase + (size_t)row * HHC + q * 4));
        mreg[i] = __ldcs((const float4*)(mbase + (size_t)row * HHC + q * 4));
        areg[i] = *(const float4*)(abase + (size_t)row * HHC + q * 4);
    }

    for (int ch = 0; ch < 128; ch++) {
        const int b = ch & 1;
        __half* Xs = smh + b * 7680;
        __half* Ah = smh + b * 7680 + 2560;
        __half* Al = smh + b * 7680 + 5120;

        // ---- STS X (fold mask & scaling) and A hi/lo ----
        #pragma unroll
        for (int i = 0; i < 2; i++) {
            int idx = t + i * 256, row = idx >> 3, q = idx & 7;
            float4 d4 = dreg[i], m4 = mreg[i];
            __half2 h0 = __floats2half2_rn(d4.x * m4.x * sc, d4.y * m4.y * sc);
            __half2 h1 = __floats2half2_rn(d4.z * m4.z * sc, d4.w * m4.w * sc);
            *(uint2*)(Xs + row * XP + q * 4) = make_uint2(h2u(h0), h2u(h1));

            float4 a4 = areg[i];
            __half2 ah0 = __floats2half2_rn(a4.x, a4.y);
            __half2 ah1 = __floats2half2_rn(a4.z, a4.w);
            float2 f0 = __half22float2(ah0), f1 = __half22float2(ah1);
            __half2 al0 = __floats2half2_rn(a4.x - f0.x, a4.y - f0.y);
            __half2 al1 = __floats2half2_rn(a4.z - f1.x, a4.w - f1.y);
            *(uint2*)(Ah + row * AP + q * 4) = make_uint2(h2u(ah0), h2u(ah1));
            *(uint2*)(Al + row * AP + q * 4) = make_uint2(h2u(al0), h2u(al1));
        }
        __syncthreads();

        // ---- prefetch next chunk ----
        if (ch + 1 < 128) {
            const int ho = (ch + 1) * 32;
            #pragma unroll
            for (int i = 0; i < 2; i++) {
                int idx = t + i * 256, row = idx >> 3, q = idx & 7;
                dreg[i] = __ldcs((const float4*)(dbase + (size_t)row * HHC + ho + q * 4));
                mreg[i] = __ldcs((const float4*)(mbase + (size_t)row * HHC + ho + q * 4));
                areg[i] = *(const float4*)(abase + (size_t)row * HHC + ho + q * 4);
            }
        }

        // ---- MMA: 2 k16 steps x 4 n-tiles x (hi+lo) ----
        #pragma unroll
        for (int s = 0; s < 2; s++) {
            const int kb = s * 16 + t4 * 2;
            uint32_t a0 = *(const uint32_t*)(Xs + row0 * XP + kb);
            uint32_t a1 = *(const uint32_t*)(Xs + (row0 + 8) * XP + kb);
            uint32_t a2 = *(const uint32_t*)(Xs + row0 * XP + kb + 8);
            uint32_t a3 = *(const uint32_t*)(Xs + (row0 + 8) * XP + kb + 8);
            #pragma unroll
            for (int j = 0; j < 4; j++) {
                const int nr = wn * 32 + j * 8 + g;
                uint32_t bh0 = *(const uint32_t*)(Ah + nr * AP + kb);
                uint32_t bh1 = *(const uint32_t*)(Ah + nr * AP + kb + 8);
                hmma16816(accT[j], a0, a1, a2, a3, bh0, bh1);
                uint32_t bl0 = *(const uint32_t*)(Al + nr * AP + kb);
                uint32_t bl1 = *(const uint32_t*)(Al + nr * AP + kb + 8);
                hmma16816(accT[j], a0, a1, a2, a3, bl0, bl1);
            }
        }
    }

    // ---- quantize T into smem ----
    __half* Ts = smh + 18432;
    #pragma unroll
    for (int j = 0; j < 4; j++) {
        const int c = wn * 32 + j * 8 + t4 * 2;
        __half2 h0 = __floats2half2_rn(accT[j][0], accT[j][1]);
        __half2 h1 = __floats2half2_rn(accT[j][2], accT[j][3]);
        *(uint32_t*)(Ts + row0 * TP + c)       = h2u(h0);
        *(uint32_t*)(Ts + (row0 + 8) * TP + c) = h2u(h1);
    }

    // ======================== PHASE 2 ========================
    // out[64, 4096] = result + T @ B^T, o-chunks of 64.
    const float* bbase = lora_b + (size_t)n * OOC * RRC;
    float4 breg[4];
    #pragma unroll
    for (int i = 0; i < 4; i++) {
        int idx = t + i * 256, row = idx >> 4, q = idx & 15;
        breg[i] = *(const float4*)(bbase + (size_t)row * RRC + q * 4);
    }
    __syncthreads();   // T visible; phase1 smem reads done before B STS

    for (int oc = 0; oc < 64; oc++) {
        const int b = oc & 1;
        __half* Bh = smh + b * 9216;
        __half* Bl = smh + b * 9216 + 4608;
        const int o0 = oc * 64;

        // ---- STS B hi/lo ----
        #pragma unroll
        for (int i = 0; i < 4; i++) {
            int idx = t + i * 256, row = idx >> 4, q = idx & 15;
            float4 a4 = breg[i];
            __half2 h0 = __floats2half2_rn(a4.x, a4.y);
            __half2 h1 = __floats2half2_rn(a4.z, a4.w);
            float2 f0 = __half22float2(h0), f1 = __half22float2(h1);
            __half2 l0 = __floats2half2_rn(a4.x - f0.x, a4.y - f0.y);
            __half2 l1 = __floats2half2_rn(a4.z - f1.x, a4.w - f1.y);
            *(uint2*)(Bh + row * BP + q * 4) = make_uint2(h2u(h0), h2u(h1));
            *(uint2*)(Bl + row * BP + q * 4) = make_uint2(h2u(l0), h2u(l1));
        }
        __syncthreads();

        // ---- prefetch next B chunk ----
        if (oc + 1 < 64) {
            const int on = (oc + 1) * 64;
            #pragma unroll
            for (int i = 0; i < 4; i++) {
                int idx = t + i * 256, row = idx >> 4, q = idx & 15;
                breg[i] = *(const float4*)(bbase + (size_t)(on + row) * RRC + q * 4);
            }
        }

        // ---- MMA: K = 64 = 4 k16 steps ----
        float acc[4][4];
        #pragma unroll
        for (int j = 0; j < 4; j++)
            #pragma unroll
            for (int k = 0; k < 4; k++) acc[j][k] = 0.f;

        #pragma unroll
        for (int s = 0; s < 4; s++) {
            const int kb = s * 16 + t4 * 2;
            uint32_t a0 = *(const uint32_t*)(Ts + row0 * TP + kb);
            uint32_t a1 = *(const uint32_t*)(Ts + (row0 + 8) * TP + kb);
            uint32_t a2 = *(const uint32_t*)(Ts + row0 * TP + kb + 8);
            uint32_t a3 = *(const uint32_t*)(Ts + (row0 + 8) * TP + kb + 8);
            #pragma unroll
            for (int j = 0; j < 4; j++) {
                const int nr = wn * 32 + j * 8 + g;
                uint32_t bh0 = *(const uint32_t*)(Bh + nr * BP + kb);
                uint32_t bh1 = *(const uint32_t*)(Bh + nr * BP + kb + 8);
                hmma16816(acc[j], a0, a1, a2, a3, bh0, bh1);
                uint32_t bl0 = *(const uint32_t*)(Bl + nr * BP + kb);
                uint32_t bl1 = *(const uint32_t*)(Bl + nr * BP + kb + 8);
                hmma16816(acc[j], a0, a1, a2, a3, bl0, bl1);
            }
        }

        // ---- epilogue: residual add + store ----
        #pragma unroll
        for (int j = 0; j < 4; j++) {
            const int ocol = o0 + wn * 32 + j * 8 + t4 * 2;
            size_t gi0 = (size_t)(m0 + row0) * OOC + ocol;
            size_t gi1 = (size_t)(m0 + row0 + 8) * OOC + ocol;
            float2 r0 = __ldcs((const float2*)(result + gi0));
            float2 r1 = __ldcs((const float2*)(result + gi1));
            __stcs((float2*)(out + gi0), make_float2(r0.x + acc[j][0], r0.y + acc[j][1]));
            __stcs((float2*)(out + gi1), make_float2(r1.x + acc[j][2], r1.y + acc[j][3]));
        }
    }
}

extern "C" void kernel_launch(void* const* d_in, const int* in_sizes, int n_in,
                              void* d_out, int out_size) {
    const float* result   = (const float*)d_in[0];
    const float* data     = (const float*)d_in[1];
    const float* mask     = (const float*)d_in[2];
    const float* lora_a   = (const float*)d_in[3];
    const float* lora_b   = (const float*)d_in[4];
    const float* scalings = (const float*)d_in[5];
    float* out = (float*)d_out;

    cudaFuncSetAttribute(lora_fused, cudaFuncAttributeMaxDynamicSharedMemorySize, SMEM_TOTAL);
    lora_fused<<<256, 256, SMEM_TOTAL>>>(result, data, mask, lora_a, lora_b, scalings, out);
}